// round 1
// baseline (speedup 1.0000x reference)
#include <cuda_runtime.h>
#include <cuda_bf16.h>

#define NN 100000   // nodes per type
#define EE 600000   // edges per relation
#define DD 128      // hidden dim

// Scratch (static device globals — no runtime allocation)
__device__ float g_y[(size_t)NN * DD];   // transformed node features (reused)
__device__ float g_u1[(size_t)NN * DD];  // layer-0 user output

// ---------------------------------------------------------------------------
// GEMM + bias + ReLU:  Y[n_rows,128] = relu(X[n_rows,128] @ W[128,128] + b)
// Block: 64 rows x 128 cols, 256 threads, each thread 8x4 outputs.
// W chunk [32][128] + X chunk [64][32] in shared, k-chunks of 32.
// ---------------------------------------------------------------------------
__global__ __launch_bounds__(256) void gemm_bias_relu(
    const float* __restrict__ X, const float* __restrict__ W,
    const float* __restrict__ bias, float* __restrict__ Y, int n_rows)
{
    __shared__ float Xs[64][32];    // [row][k]
    __shared__ float Ws[32][128];   // [k][col]

    const int tid  = threadIdx.x;
    const int w    = tid >> 5;   // 0..7  -> row group (warp-uniform)
    const int lane = tid & 31;   // 0..31 -> col group (4 cols)
    const int row0 = blockIdx.x * 64;

    float acc[8][4];
#pragma unroll
    for (int i = 0; i < 8; i++)
#pragma unroll
        for (int j = 0; j < 4; j++) acc[i][j] = 0.f;

    for (int k0 = 0; k0 < DD; k0 += 32) {
        // Load Xs: 64x32 floats = 512 float4, 2 per thread
#pragma unroll
        for (int t = 0; t < 2; t++) {
            int f4 = tid + t * 256;        // 0..511
            int r  = f4 >> 3;              // 0..63
            int kk = (f4 & 7) << 2;        // 0,4,...,28
            float4 v = make_float4(0.f, 0.f, 0.f, 0.f);
            int gr = row0 + r;
            if (gr < n_rows)
                v = *reinterpret_cast<const float4*>(X + (size_t)gr * DD + k0 + kk);
            *reinterpret_cast<float4*>(&Xs[r][kk]) = v;
        }
        // Load Ws: 32x128 floats = 1024 float4, 4 per thread (coalesced, no transpose)
#pragma unroll
        for (int t = 0; t < 4; t++) {
            int f4 = tid + t * 256;        // 0..1023
            int kk = f4 >> 5;              // 0..31
            int c  = (f4 & 31) << 2;       // 0..124
            *reinterpret_cast<float4*>(&Ws[kk][c]) =
                *reinterpret_cast<const float4*>(W + (size_t)(k0 + kk) * DD + c);
        }
        __syncthreads();

#pragma unroll
        for (int k = 0; k < 32; k++) {
            float4 bv = *reinterpret_cast<const float4*>(&Ws[k][lane << 2]);
#pragma unroll
            for (int i = 0; i < 8; i++) {
                float a = Xs[(w << 3) + i][k];   // warp-uniform broadcast
                acc[i][0] = fmaf(a, bv.x, acc[i][0]);
                acc[i][1] = fmaf(a, bv.y, acc[i][1]);
                acc[i][2] = fmaf(a, bv.z, acc[i][2]);
                acc[i][3] = fmaf(a, bv.w, acc[i][3]);
            }
        }
        __syncthreads();
    }

    float4 bb = *reinterpret_cast<const float4*>(bias + (lane << 2));
#pragma unroll
    for (int i = 0; i < 8; i++) {
        int r = row0 + (w << 3) + i;
        if (r < n_rows) {
            float4 o;
            o.x = fmaxf(acc[i][0] + bb.x, 0.f);
            o.y = fmaxf(acc[i][1] + bb.y, 0.f);
            o.z = fmaxf(acc[i][2] + bb.z, 0.f);
            o.w = fmaxf(acc[i][3] + bb.w, 0.f);
            *reinterpret_cast<float4*>(Y + (size_t)r * DD + (lane << 2)) = o;
        }
    }
}

// ---------------------------------------------------------------------------
// Scatter-add: out[dst[e]] += Y[src[e]]  for each edge, one warp per edge.
// 32 lanes x float4 = full 512B row, coalesced gather + vector red atomic.
// ---------------------------------------------------------------------------
__global__ __launch_bounds__(256) void scatter_add_edges(
    const float* __restrict__ Y, const int* __restrict__ src,
    const int* __restrict__ dst, float* __restrict__ out, int n_edges)
{
    int e    = (int)((blockIdx.x * (unsigned)blockDim.x + threadIdx.x) >> 5);
    int lane = threadIdx.x & 31;
    if (e >= n_edges) return;

    int s = __ldg(src + e);
    int d = __ldg(dst + e);

    float4 v = *(reinterpret_cast<const float4*>(Y + (size_t)s * DD) + lane);
    float* o = out + (size_t)d * DD + (lane << 2);
    asm volatile("red.global.add.v4.f32 [%0], {%1,%2,%3,%4};"
                 :: "l"(o), "f"(v.x), "f"(v.y), "f"(v.z), "f"(v.w)
                 : "memory");
}

// ---------------------------------------------------------------------------
extern "C" void kernel_launch(void* const* d_in, const int* in_sizes, int n_in,
                              void* d_out, int out_size)
{
    // Classify inputs by element count (robust to metadata ordering; within-class
    // order matches reference: x_user,x_item | ei_follows,ei_rates | W0f,W0r,W1f,W1r | b...)
    const float* x_user = nullptr;
    const int*   ei_f   = nullptr;
    const int*   ei_r   = nullptr;
    const float* Wm[4]  = {nullptr, nullptr, nullptr, nullptr};
    const float* bm[4]  = {nullptr, nullptr, nullptr, nullptr};
    int xcnt = 0, ecnt = 0, wcnt = 0, bcnt = 0;

    for (int i = 0; i < n_in; i++) {
        int sz = in_sizes[i];
        if (sz == NN * DD) {
            if (xcnt == 0) x_user = (const float*)d_in[i];
            xcnt++;                       // x_item is dead code in the reference
        } else if (sz == 2 * EE) {
            if (ecnt == 0) ei_f = (const int*)d_in[i];
            else           ei_r = (const int*)d_in[i];
            ecnt++;
        } else if (sz == DD * DD) {
            if (wcnt < 4) Wm[wcnt] = (const float*)d_in[i];
            wcnt++;
        } else if (sz == DD) {
            if (bcnt < 4) bm[bcnt] = (const float*)d_in[i];
            bcnt++;
        }
    }

    float* y;  cudaGetSymbolAddress((void**)&y,  g_y);
    float* u1; cudaGetSymbolAddress((void**)&u1, g_u1);

    float* out_xu = (float*)d_out;
    float* out_xi = (float*)d_out + (size_t)NN * DD;

    const int gemm_blocks = (NN + 63) / 64;
    const int scat_blocks = (EE * 32 + 255) / 256;

    // Accumulators must start at zero (d_out is poisoned by the harness)
    cudaMemsetAsync(u1,    0, (size_t)NN * DD * sizeof(float), 0);
    cudaMemsetAsync(d_out, 0, (size_t)out_size * sizeof(float), 0);

    // Layer 0 (only the 'follows' conv is live):
    //   u1 = segsum_follows(relu(x_user @ W0f + b0f))
    gemm_bias_relu<<<gemm_blocks, 256>>>(x_user, Wm[0], bm[0], y, NN);
    scatter_add_edges<<<scat_blocks, 256>>>(y, ei_f, ei_f + EE, u1, EE);

    // Layer 1 'follows': out_xu = segsum_follows(relu(u1 @ W1f + b1f))
    gemm_bias_relu<<<gemm_blocks, 256>>>(u1, Wm[2], bm[2], y, NN);
    scatter_add_edges<<<scat_blocks, 256>>>(y, ei_f, ei_f + EE, out_xu, EE);

    // Layer 1 'rates':   out_xi = segsum_rates(relu(u1 @ W1r + b1r))
    gemm_bias_relu<<<gemm_blocks, 256>>>(u1, Wm[3], bm[3], y, NN);
    scatter_add_edges<<<scat_blocks, 256>>>(y, ei_r, ei_r + EE, out_xi, EE);
}